// round 5
// baseline (speedup 1.0000x reference)
#include <cuda_runtime.h>
#include <math.h>
#include <stdint.h>

#define B_    32
#define L_    512
#define H_    256
#define E_    300
#define NH    8
#define HD    32
#define NITER 6
#define L1    513
#define M1    (B_*L_)        // 16384
#define M2    (B_*L1)        // 16416

// ---------------- scratch ----------------
__device__ float d_nodes[M1*H_];
__device__ float d_u    [M1*H_];     // unmasked updated nodes
__device__ float d_q    [M1*H_];
__device__ float d_k    [M1*H_];
__device__ float d_att  [M1*H_];
__device__ float d_k2   [M2*H_];
__device__ float d_v2   [M2*H_];
__device__ float d_relay[B_*H_];
__device__ float d_ak   [B_*H_];
__device__ float d_av   [B_*H_];
__device__ float d_q2   [B_*H_];
__device__ float d_att2 [B_*H_];
__device__ float d_part [B_*16*H_];
__device__ float d_mu   [M1];
__device__ float d_rs   [M1];

// =====================================================================
// Unified TF32 tensor-core GEMM, cp.async double-buffered,
// in-place tile transform (cvt / LayerNorm) after async wait.
// MODE 0 (QK): dual output, A = LN(nodes) computed in transform pass
// MODE 1 (O):  single, u = nodes + leaky(acc+b); write u and masked nodes
// MODE 2 (KV): dual output, row-remap r -> r + r/512 + 1
// MODE 3 (EMB): single, A gathered from emb[data[r]], K=300, +pos epilogue
// =====================================================================
#define TBM 128
#define TBN 128
#define TBK 32
#define ASTR 36
// floats: A 2*128*36 | B 2*32*128 | mu/rs 128*2 | g/b 256*2
#define SM_A   0
#define SM_B   (2*TBM*ASTR)
#define SM_MU  (SM_B + 2*TBK*TBN)
#define SM_RS  (SM_MU + 128)
#define SM_G   (SM_RS + 128)
#define SM_BB  (SM_G + 256)
#define GEMM_SMEM ((SM_BB + 256) * 4)

__device__ __forceinline__ uint32_t f2tf32(float x) {
    uint32_t r;
    asm("cvt.rna.tf32.f32 %0, %1;" : "=r"(r) : "f"(x));
    return r;
}

__device__ __forceinline__ void mma_tf32(float c[4],
                                         uint32_t a0, uint32_t a1, uint32_t a2, uint32_t a3,
                                         uint32_t b0, uint32_t b1)
{
    asm volatile(
        "mma.sync.aligned.m16n8k8.row.col.f32.tf32.tf32.f32 "
        "{%0,%1,%2,%3}, {%4,%5,%6,%7}, {%8,%9}, {%0,%1,%2,%3};"
        : "+f"(c[0]), "+f"(c[1]), "+f"(c[2]), "+f"(c[3])
        : "r"(a0), "r"(a1), "r"(a2), "r"(a3), "r"(b0), "r"(b1));
}

__device__ __forceinline__ void cpa16(uint32_t dst, const void* src, bool ok) {
    int sz = ok ? 16 : 0;
    asm volatile("cp.async.cg.shared.global [%0], [%1], 16, %2;"
                 :: "r"(dst), "l"(src), "r"(sz));
}

template<int MODE>
__global__ void __launch_bounds__(256, 2)
gemm_uni(const float* __restrict__ A,
         const float* __restrict__ W1, const float* __restrict__ b1, float* __restrict__ C1,
         const float* __restrict__ W2, const float* __restrict__ b2, float* __restrict__ C2,
         const float* __restrict__ pos, const int* __restrict__ tok,
         const float* __restrict__ emb, float* __restrict__ uOut,
         float* __restrict__ nodes,
         const float* __restrict__ muG, const float* __restrict__ rsG,
         const float* __restrict__ lnG, const float* __restrict__ lnB)
{
    constexpr int  K    = (MODE == 3) ? 300 : 256;
    constexpr int  NKT  = (K + TBK - 1) / TBK;
    constexpr bool DUAL = (MODE == 0 || MODE == 2);

    extern __shared__ float sm[];
    float* As = sm + SM_A;
    float* Bs = sm + SM_B;
    uint32_t aS = (uint32_t)__cvta_generic_to_shared(As);
    uint32_t bS = (uint32_t)__cvta_generic_to_shared(Bs);

    const int tid = threadIdx.x;
    const int m0  = blockIdx.x * TBM;

    const float *W, *bias; float* C;
    int n0;
    if (DUAL) {
        bool sec = (blockIdx.y >> 1);
        W = sec ? W2 : W1; bias = sec ? b2 : b1; C = sec ? C2 : C1;
        n0 = (blockIdx.y & 1) * TBN;
    } else {
        W = W1; bias = b1; C = C1;
        n0 = blockIdx.y * TBN;
    }

    // preload LN params for mode 0
    if (MODE == 0) {
        if (tid < 128) {
            sm[SM_MU + tid] = muG[m0 + tid];
            sm[SM_RS + tid] = rsG[m0 + tid];
        }
        sm[SM_G + tid] = lnG[tid];
        sm[SM_BB + tid] = lnB[tid];
    }

    // per-thread load slots (4 x 16B for A, 4 x 16B for B)
    const float* aSrc[4]; uint32_t aDst[4]; int aR[4], aCC[4];
    const float* bSrc[4]; uint32_t bDst[4]; int bR[4];
    uint32_t bOffLocal[4];
#pragma unroll
    for (int p = 0; p < 4; p++) {
        int j = tid + p * 256;
        int r = j >> 3, cc = (j & 7) * 4;
        if (MODE == 3) aSrc[p] = emb + (size_t)__ldg(tok + m0 + r) * E_ + cc;
        else           aSrc[p] = A + (size_t)(m0 + r) * 256 + cc;
        aDst[p] = aS + (uint32_t)(r * ASTR + cc) * 4;
        aR[p] = r; aCC[p] = cc;
        int rb = j >> 5, cb = (j & 31) * 4;
        bSrc[p] = W + (size_t)rb * 256 + n0 + cb;
        bOffLocal[p] = (uint32_t)(rb * TBN + (cb ^ (8 * (rb & 3))));
        bDst[p] = bS + bOffLocal[p] * 4;
        bR[p]   = rb;
    }

    const int warp = tid >> 5, lane = tid & 31;
    const int gid = lane >> 2, tig = lane & 3;
    const int warpM = warp >> 2, warpN = warp & 3;

    float acc[4][4][4];
#pragma unroll
    for (int i = 0; i < 4; i++)
#pragma unroll
        for (int j = 0; j < 4; j++)
#pragma unroll
            for (int r = 0; r < 4; r++) acc[i][j][r] = 0.f;

    const uint32_t aBufB = TBM * ASTR * 4;
    const uint32_t bBufB = TBK * TBN * 4;

    // prologue: tile 0
#pragma unroll
    for (int p = 0; p < 4; p++) {
        cpa16(aDst[p], aSrc[p], true);
        cpa16(bDst[p], bSrc[p], true);
    }
    asm volatile("cp.async.commit_group;");

    for (int kb = 0; kb < NKT; kb++) {
        int kn = (kb + 1) * TBK;
        if (kb + 1 < NKT) {
            uint32_t aO = ((kb + 1) & 1) * aBufB;
            uint32_t bO = ((kb + 1) & 1) * bBufB;
#pragma unroll
            for (int p = 0; p < 4; p++) {
                bool okA = (MODE != 3) || (kn + aCC[p] < K);
                cpa16(aDst[p] + aO, aSrc[p] + kn, okA);
                bool okB = (MODE != 3) || (kn + bR[p] < K);
                cpa16(bDst[p] + bO, bSrc[p] + (size_t)kn * 256, okB);
            }
        }
        asm volatile("cp.async.commit_group;");
        asm volatile("cp.async.wait_group 1;");
        __syncthreads();

        float* Ab = As + (kb & 1) * (TBM * ASTR);
        float* Bb = Bs + (kb & 1) * (TBK * TBN);

        // ---- in-place transform: cvt (and LN for mode 0) ----
#pragma unroll
        for (int p = 0; p < 4; p++) {
            float* ap = Ab + aR[p] * ASTR + aCC[p];
            float4 v = *(float4*)ap;
            if (MODE == 0) {
                float mu = sm[SM_MU + aR[p]], rsv = sm[SM_RS + aR[p]];
                int gc = kb * TBK + aCC[p];
                v.x = sm[SM_G + gc + 0] * ((v.x - mu) * rsv) + sm[SM_BB + gc + 0];
                v.y = sm[SM_G + gc + 1] * ((v.y - mu) * rsv) + sm[SM_BB + gc + 1];
                v.z = sm[SM_G + gc + 2] * ((v.z - mu) * rsv) + sm[SM_BB + gc + 2];
                v.w = sm[SM_G + gc + 3] * ((v.w - mu) * rsv) + sm[SM_BB + gc + 3];
            }
            ap[0] = __uint_as_float(f2tf32(v.x));
            ap[1] = __uint_as_float(f2tf32(v.y));
            ap[2] = __uint_as_float(f2tf32(v.z));
            ap[3] = __uint_as_float(f2tf32(v.w));
            float* bp = Bb + bOffLocal[p];
            float4 w = *(float4*)bp;
            bp[0] = __uint_as_float(f2tf32(w.x));
            bp[1] = __uint_as_float(f2tf32(w.y));
            bp[2] = __uint_as_float(f2tf32(w.z));
            bp[3] = __uint_as_float(f2tf32(w.w));
        }
        __syncthreads();

#pragma unroll
        for (int ks = 0; ks < 4; ks++) {
            const int k0 = ks * 8;
            const int xr = 8 * tig;
            uint32_t bf0[4], bf1[4];
#pragma unroll
            for (int nf = 0; nf < 4; nf++) {
                int cb = warpN * 32 + nf * 8 + gid;
                int pc = cb ^ xr;
                bf0[nf] = __float_as_uint(Bb[(k0 + tig) * TBN + pc]);
                bf1[nf] = __float_as_uint(Bb[(k0 + tig + 4) * TBN + pc]);
            }
#pragma unroll
            for (int mf = 0; mf < 4; mf++) {
                int rb = warpM * 64 + mf * 16;
                uint32_t a0 = __float_as_uint(Ab[(rb + gid)     * ASTR + k0 + tig]);
                uint32_t a1 = __float_as_uint(Ab[(rb + gid + 8) * ASTR + k0 + tig]);
                uint32_t a2 = __float_as_uint(Ab[(rb + gid)     * ASTR + k0 + tig + 4]);
                uint32_t a3 = __float_as_uint(Ab[(rb + gid + 8) * ASTR + k0 + tig + 4]);
#pragma unroll
                for (int nf = 0; nf < 4; nf++)
                    mma_tf32(acc[mf][nf], a0, a1, a2, a3, bf0[nf], bf1[nf]);
            }
        }
        __syncthreads();
    }

    // ---- epilogue ----
#pragma unroll
    for (int mf = 0; mf < 4; mf++) {
        int r0i = m0 + warpM * 64 + mf * 16 + gid;
        int r1i = r0i + 8;
        int o0 = r0i, o1 = r1i;
        if (MODE == 2) { o0 = r0i + (r0i >> 9) + 1; o1 = r1i + (r1i >> 9) + 1; }
        int msk0 = 0, msk1 = 0;
        if (MODE == 1) { msk0 = (__ldg(tok + r0i) == 1); msk1 = (__ldg(tok + r1i) == 1); }
#pragma unroll
        for (int nf = 0; nf < 4; nf++) {
            int col = n0 + warpN * 32 + nf * 8 + tig * 2;
            float2 bv = *(const float2*)(bias + col);
            float x0 = acc[mf][nf][0] + bv.x;
            float x1 = acc[mf][nf][1] + bv.y;
            float x2 = acc[mf][nf][2] + bv.x;
            float x3 = acc[mf][nf][3] + bv.y;
            if (MODE == 3) {
                float2 p0 = *(const float2*)(pos + (size_t)(r0i & 511) * 256 + col);
                float2 p1 = *(const float2*)(pos + (size_t)(r1i & 511) * 256 + col);
                x0 += p0.x; x1 += p0.y; x2 += p1.x; x3 += p1.y;
            }
            if (MODE == 1) {
                x0 = x0 > 0.f ? x0 : 0.01f * x0;
                x1 = x1 > 0.f ? x1 : 0.01f * x1;
                x2 = x2 > 0.f ? x2 : 0.01f * x2;
                x3 = x3 > 0.f ? x3 : 0.01f * x3;
                float2 old0 = *(const float2*)(nodes + (size_t)r0i * 256 + col);
                float2 old1 = *(const float2*)(nodes + (size_t)r1i * 256 + col);
                float u0 = old0.x + x0, u1 = old0.y + x1;
                float u2 = old1.x + x2, u3 = old1.y + x3;
                *(float2*)(uOut + (size_t)r0i * 256 + col) = make_float2(u0, u1);
                *(float2*)(uOut + (size_t)r1i * 256 + col) = make_float2(u2, u3);
                *(float2*)(nodes + (size_t)r0i * 256 + col) =
                    msk0 ? make_float2(0.f, 0.f) : make_float2(u0, u1);
                *(float2*)(nodes + (size_t)r1i * 256 + col) =
                    msk1 ? make_float2(0.f, 0.f) : make_float2(u2, u3);
            } else {
                *(float2*)(C + (size_t)o0 * 256 + col) = make_float2(x0, x1);
                *(float2*)(C + (size_t)o1 * 256 + col) = make_float2(x2, x3);
            }
        }
    }
}

// ---------------- LN statistics only: mu, rstd per token ----------------
__global__ void __launch_bounds__(256)
ln_stats(const float* __restrict__ x, float* __restrict__ mu, float* __restrict__ rs)
{
    int warp = threadIdx.x >> 5, lane = threadIdx.x & 31;
    int tok = blockIdx.x * 8 + warp;
    const float* xr = x + (size_t)tok * H_;
    float4 v0 = *(const float4*)(xr + lane * 8);
    float4 v1 = *(const float4*)(xr + lane * 8 + 4);
    float s = v0.x + v0.y + v0.z + v0.w + v1.x + v1.y + v1.z + v1.w;
#pragma unroll
    for (int o = 16; o; o >>= 1) s += __shfl_xor_sync(0xffffffffu, s, o);
    float m = s * (1.f / H_);
    float d0 = v0.x - m, d1 = v0.y - m, d2 = v0.z - m, d3 = v0.w - m;
    float d4 = v1.x - m, d5 = v1.y - m, d6 = v1.z - m, d7 = v1.w - m;
    float q = d0*d0 + d1*d1 + d2*d2 + d3*d3 + d4*d4 + d5*d5 + d6*d6 + d7*d7;
#pragma unroll
    for (int o = 16; o; o >>= 1) q += __shfl_xor_sync(0xffffffffu, q, o);
    if (lane == 0) {
        mu[tok] = m;
        rs[tok] = rsqrtf(q * (1.f / H_) + 1e-5f);
    }
}

// ---------------- batched small row GEMMs (up to 5 outputs via gridDim.y) ----
__global__ void __launch_bounds__(1024)
small5(const float* __restrict__ A,
       const float* __restrict__ W0, const float* __restrict__ bi0, float* __restrict__ C0, int ld0,
       const float* __restrict__ W1, const float* __restrict__ bi1, float* __restrict__ C1, int ld1,
       const float* __restrict__ W2, const float* __restrict__ bi2, float* __restrict__ C2, int ld2,
       const float* __restrict__ W3, const float* __restrict__ bi3, float* __restrict__ C3, int ld3,
       const float* __restrict__ W4, const float* __restrict__ bi4, float* __restrict__ C4, int ld4,
       int leaky)
{
    __shared__ float sa[H_];
    __shared__ float part[4][H_];
    const float *W, *bi; float* C; int ld;
    switch (blockIdx.y) {
        case 0: W = W0; bi = bi0; C = C0; ld = ld0; break;
        case 1: W = W1; bi = bi1; C = C1; ld = ld1; break;
        case 2: W = W2; bi = bi2; C = C2; ld = ld2; break;
        case 3: W = W3; bi = bi3; C = C3; ld = ld3; break;
        default: W = W4; bi = bi4; C = C4; ld = ld4; break;
    }
    int m = blockIdx.x;
    int n = threadIdx.x & 255, ks = threadIdx.x >> 8;
    if (threadIdx.x < H_) sa[threadIdx.x] = A[(size_t)m * H_ + threadIdx.x];
    __syncthreads();
    float acc = 0.f;
    int k0 = ks * 64;
#pragma unroll 8
    for (int k = k0; k < k0 + 64; k++) acc += sa[k] * W[(size_t)k * H_ + n];
    part[ks][n] = acc;
    __syncthreads();
    if (ks == 0) {
        float r = part[0][n] + part[1][n] + part[2][n] + part[3][n] + bi[n];
        if (leaky) r = r > 0.f ? r : 0.01f * r;
        C[(size_t)m * ld + n] = r;
    }
}

// ---------------- ring attention (msa1) ----------------
__global__ void msa1_attn(const float* __restrict__ q, const float* __restrict__ k,
                          const float* __restrict__ ak, const float* __restrict__ av,
                          float* __restrict__ att)
{
    int token = blockIdx.x;
    int b = token >> 9;
    int l = token & 511;
    int h = threadIdx.x >> 5;
    int d = threadIdx.x & 31;
    int off = h * HD + d;

    float qd  = q[(size_t)token * H_ + off];
    float akd = ak[b * H_ + off];
    float avd = av[b * H_ + off];
    float km1 = (l > 0)      ? k[(size_t)(token - 1) * H_ + off] : 0.f;
    float k0v =                k[(size_t)token * H_ + off];
    float kp1 = (l < L_ - 1) ? k[(size_t)(token + 1) * H_ + off] : 0.f;

    float s0 = qd * akd, s1 = qd * km1, s2 = qd * k0v, s3 = qd * kp1;
#pragma unroll
    for (int o = 16; o; o >>= 1) {
        s0 += __shfl_xor_sync(0xffffffffu, s0, o);
        s1 += __shfl_xor_sync(0xffffffffu, s1, o);
        s2 += __shfl_xor_sync(0xffffffffu, s2, o);
        s3 += __shfl_xor_sync(0xffffffffu, s3, o);
    }
    const float sc = 0.17677669529663687f;
    s0 *= sc; s1 *= sc; s2 *= sc; s3 *= sc;
    float mx = fmaxf(fmaxf(s0, s1), fmaxf(s2, s3));
    float e0 = expf(s0 - mx), e1 = expf(s1 - mx), e2 = expf(s2 - mx), e3 = expf(s3 - mx);
    float inv = 1.f / (e0 + e1 + e2 + e3);
    att[(size_t)token * H_ + off] = (e0 * avd + e1 * km1 + e2 * k0v + e3 * kp1) * inv;
}

// ---------------- relay attention (msa2), coalesced scores ----------------
__global__ void __launch_bounds__(256)
msa2_attn(const float* __restrict__ q2, const float* __restrict__ k2,
          const float* __restrict__ v2, float* __restrict__ att2)
{
    __shared__ float sq[HD];
    __shared__ float scs[L1];
    __shared__ float red[256];
    __shared__ float part[8][HD];
    int b = blockIdx.x >> 3, h = blockIdx.x & 7;
    int t = threadIdx.x, w = t >> 5, lane = t & 31;

    if (t < HD) sq[t] = q2[b * H_ + h * HD + t];
    __syncthreads();

    for (int j = w; j < L1; j += 8) {
        float v = k2[((size_t)(b * L1 + j)) * H_ + h * HD + lane] * sq[lane];
#pragma unroll
        for (int o = 16; o; o >>= 1) v += __shfl_xor_sync(0xffffffffu, v, o);
        if (lane == 0) scs[j] = v * 0.17677669529663687f;
    }
    __syncthreads();

    float m = -3.4e38f;
    for (int j = t; j < L1; j += 256) m = fmaxf(m, scs[j]);
    red[t] = m;
    __syncthreads();
    for (int s = 128; s > 0; s >>= 1) { if (t < s) red[t] = fmaxf(red[t], red[t + s]); __syncthreads(); }
    m = red[0];
    __syncthreads();

    float sum = 0.f;
    for (int j = t; j < L1; j += 256) { float e = expf(scs[j] - m); scs[j] = e; sum += e; }
    red[t] = sum;
    __syncthreads();
    for (int s = 128; s > 0; s >>= 1) { if (t < s) red[t] += red[t + s]; __syncthreads(); }
    float inv = 1.f / red[0];
    __syncthreads();

    float acc = 0.f;
    for (int j = w; j < L1; j += 8)
        acc += scs[j] * v2[((size_t)(b * L1 + j)) * H_ + h * HD + lane];
    part[w][lane] = acc;
    __syncthreads();
    if (t < HD) {
        float s = 0.f;
#pragma unroll
        for (int g2 = 0; g2 < 8; g2++) s += part[g2][t];
        att2[b * H_ + h * HD + t] = s * inv;
    }
}

// ---------------- two-stage mean / max ----------------
__global__ void mean_part_k(const float* __restrict__ x, float* __restrict__ part)
{
    int b = blockIdx.x, c = blockIdx.y, d = threadIdx.x;
    float s = 0.f;
#pragma unroll 8
    for (int l = c * 32; l < c * 32 + 32; l++)
        s += x[((size_t)(b * L_ + l)) * H_ + d];
    part[(size_t)(b * 16 + c) * H_ + d] = s;
}
__global__ void mean_comb_k(const float* __restrict__ part, float* __restrict__ relay)
{
    int b = blockIdx.x, d = threadIdx.x;
    float s = 0.f;
#pragma unroll
    for (int c = 0; c < 16; c++) s += part[(size_t)(b * 16 + c) * H_ + d];
    relay[b * H_ + d] = s * (1.f / L_);
}
__global__ void max_part_k(const float* __restrict__ x, float* __restrict__ part)
{
    int b = blockIdx.x, c = blockIdx.y, d = threadIdx.x;
    float s = -3.4e38f;
#pragma unroll 8
    for (int l = c * 32; l < c * 32 + 32; l++)
        s = fmaxf(s, x[((size_t)(b * L_ + l)) * H_ + d]);
    part[(size_t)(b * 16 + c) * H_ + d] = s;
}
__global__ void final_comb_k(const float* __restrict__ part, const float* __restrict__ relay,
                             float* __restrict__ out)
{
    int b = blockIdx.x, d = threadIdx.x;
    float s = -3.4e38f;
#pragma unroll
    for (int c = 0; c < 16; c++) s = fmaxf(s, part[(size_t)(b * 16 + c) * H_ + d]);
    out[b * H_ + d] = 0.5f * s + 0.5f * relay[b * H_ + d];
}

// ---------------- host ----------------
template <typename T>
static float* sym_addr(T& sym)
{
    void* p = nullptr;
    cudaGetSymbolAddress(&p, sym);
    return (float*)p;
}

extern "C" void kernel_launch(void* const* d_in, const int* in_sizes, int n_in,
                              void* d_out, int out_size)
{
    const int*   data = (const int*)d_in[0];
    const float* emb  = (const float*)d_in[1];
    const float* fcW  = (const float*)d_in[2];
    const float* fcb  = (const float*)d_in[3];
    const float* pos  = (const float*)d_in[4];
    const float* lng  = (const float*)d_in[5];
    const float* lnb  = (const float*)d_in[6];
    const float* rWQ = (const float*)d_in[7],  *rbQ = (const float*)d_in[8];
    const float* rWK = (const float*)d_in[9],  *rbK = (const float*)d_in[10];
    const float* rWV = (const float*)d_in[11], *rbV = (const float*)d_in[12];
    const float* rWO = (const float*)d_in[13], *rbO = (const float*)d_in[14];
    const float* sWQ = (const float*)d_in[15], *sbQ = (const float*)d_in[16];
    const float* sWK = (const float*)d_in[17], *sbK = (const float*)d_in[18];
    const float* sWV = (const float*)d_in[19], *sbV = (const float*)d_in[20];
    const float* sWO = (const float*)d_in[21], *sbO = (const float*)d_in[22];
    float* out = (float*)d_out;

    float* nodes = sym_addr(d_nodes);
    float* u     = sym_addr(d_u);
    float* q     = sym_addr(d_q);
    float* kbuf  = sym_addr(d_k);
    float* att   = sym_addr(d_att);
    float* k2    = sym_addr(d_k2);
    float* v2    = sym_addr(d_v2);
    float* relay = sym_addr(d_relay);
    float* ak    = sym_addr(d_ak);
    float* av    = sym_addr(d_av);
    float* q2    = sym_addr(d_q2);
    float* att2  = sym_addr(d_att2);
    float* part  = sym_addr(d_part);
    float* muB   = sym_addr(d_mu);
    float* rsB   = sym_addr(d_rs);

    cudaFuncSetAttribute(gemm_uni<0>, cudaFuncAttributeMaxDynamicSharedMemorySize, GEMM_SMEM);
    cudaFuncSetAttribute(gemm_uni<1>, cudaFuncAttributeMaxDynamicSharedMemorySize, GEMM_SMEM);
    cudaFuncSetAttribute(gemm_uni<2>, cudaFuncAttributeMaxDynamicSharedMemorySize, GEMM_SMEM);
    cudaFuncSetAttribute(gemm_uni<3>, cudaFuncAttributeMaxDynamicSharedMemorySize, GEMM_SMEM);

    const dim3 gDual(M1 / TBM, 4);
    const dim3 gSingle(M1 / TBM, 2);

    // x0 = emb[data] @ fcW + fcb + pos   (gather fused into A loader)
    gemm_uni<3><<<gSingle, 256, GEMM_SMEM>>>(nullptr, fcW, fcb, nodes,
                                             nullptr, nullptr, nullptr,
                                             pos, data, emb, nullptr, nullptr,
                                             nullptr, nullptr, nullptr, nullptr);
    mean_part_k<<<dim3(B_, 16), 256>>>(nodes, part);
    mean_comb_k<<<B_, 256>>>(part, relay);

    for (int i = 0; i < NITER; i++) {
        const size_t wo = (size_t)i * H_ * H_;
        const size_t bo = (size_t)i * H_;

        // all 5 relay-row projections in one launch (relay fixed for the iter)
        small5<<<dim3(B_, 5), 1024>>>(relay,
                                      rWK + wo, rbK + bo, ak, H_,
                                      rWV + wo, rbV + bo, av, H_,
                                      sWQ + wo, sbQ + bo, q2, H_,
                                      sWK + wo, sbK + bo, k2, L1 * H_,
                                      sWV + wo, sbV + bo, v2, L1 * H_, 0);
        ln_stats<<<M1 / 8, 256>>>(nodes, muB, rsB);
        // Q/K projections of LN(nodes); LN applied in the A transform pass
        gemm_uni<0><<<gDual, 256, GEMM_SMEM>>>(nodes, rWQ + wo, rbQ + bo, q,
                                               rWK + wo, rbK + bo, kbuf,
                                               nullptr, nullptr, nullptr, nullptr, nullptr,
                                               muB, rsB, lng + bo, lnb + bo);
        msa1_attn<<<M1, 256>>>(q, kbuf, ak, av, att);
        gemm_uni<1><<<gSingle, 256, GEMM_SMEM>>>(att, rWO + wo, rbO + bo, nullptr,
                                                 nullptr, nullptr, nullptr,
                                                 nullptr, data, nullptr, u, nodes,
                                                 nullptr, nullptr, nullptr, nullptr);
        // node rows of k2/v2 (row remap fused into epilogue)
        gemm_uni<2><<<gDual, 256, GEMM_SMEM>>>(u, sWK + wo, sbK + bo, k2,
                                               sWV + wo, sbV + bo, v2,
                                               nullptr, nullptr, nullptr, nullptr, nullptr,
                                               nullptr, nullptr, nullptr, nullptr);
        msa2_attn<<<B_ * NH, 256>>>(q2, k2, v2, att2);
        small5<<<dim3(B_, 1), 1024>>>(att2,
                                      sWO + wo, sbO + bo, relay, H_,
                                      nullptr, nullptr, nullptr, 0,
                                      nullptr, nullptr, nullptr, 0,
                                      nullptr, nullptr, nullptr, 0,
                                      nullptr, nullptr, nullptr, 0, 1);
    }

    max_part_k<<<dim3(B_, 16), 256>>>(nodes, part);
    final_comb_k<<<B_, 256>>>(part, relay, out);
}